// round 3
// baseline (speedup 1.0000x reference)
#include <cuda_runtime.h>

#define Vdim   96
#define Kdim   20
#define Bdim   256
#define Ddim   1024
#define GROUPS 144      // 3*3*4*2*2
#define NIJ    9
#define VK     1920     // Vdim*Kdim

// ---- scratch (static device globals — no runtime allocation) ----
__device__ float g_A[NIJ * VK];          // sum over (e,n,c,b)   -> [ij][v][k]
__device__ float g_G[GROUPS * Kdim];     // sum over (b,v)       -> [ij,e,n,c][k]
__device__ float g_Wb[NIJ * Bdim];       // sum over (e,n,c,v,k) -> [ij][b]
__device__ float g_ytr[NIJ * Ddim];      // sum over (e,n,c,v) of Y -> [ij][d]

__global__ void zero_scratch() {
    int i = blockIdx.x * blockDim.x + threadIdx.x;
    if (i < NIJ * VK)      g_A[i]  = 0.f;
    if (i < GROUPS * Kdim) g_G[i]  = 0.f;
    if (i < NIJ * Bdim)    g_Wb[i] = 0.f;
}

// ---------------------------------------------------------------------------
// Kernel 2: reduce Y -> ytr[ij][d] = sum over (e,n,c,v)
// Y layout: (3,3,4,2,2,D,V); for fixed (ij): enc stride = D*V, d stride = V.
// ---------------------------------------------------------------------------
__global__ __launch_bounds__(96) void reduce_Y(const float* __restrict__ Yv) {
    int blk = blockIdx.x;            // blk = ij*Ddim + d
    int ij  = blk / Ddim;
    int d   = blk - ij * Ddim;
    int t   = threadIdx.x;           // 0..95 = v
    const float* base = Yv + (size_t)ij * (16 * Ddim * Vdim) + (size_t)d * Vdim + t;
    float s = 0.f;
#pragma unroll
    for (int enc = 0; enc < 16; ++enc) s += base[(size_t)enc * Ddim * Vdim];
#pragma unroll
    for (int off = 16; off; off >>= 1) s += __shfl_down_sync(0xffffffffu, s, off);
    __shared__ float sm[3];
    if ((t & 31) == 0) sm[t >> 5] = s;
    __syncthreads();
    if (t == 0) g_ytr[blk] = sm[0] + sm[1] + sm[2];
}

// ---------------------------------------------------------------------------
// Kernel 3: stream yphi once -> A, G, Wb
// yphi layout: (3,3,e,n,c,B,V,K). group = ij*16 + enc (144 groups).
// 320 threads = 16*20: thread t has fixed k = t%20, a = t/20;
// its 6 elements per b are v = a + 16*m  (m<6), at stride 320 floats (coalesced).
// ---------------------------------------------------------------------------
#define BPB    64               // b's per block
#define SPLITS (Bdim / BPB)     // 4
#define T1     320

__global__ __launch_bounds__(T1) void reduce_yphi(const float* __restrict__ yphi) {
    int blk    = blockIdx.x;               // 0..575
    int group  = blk / SPLITS;             // 0..143
    int bsplit = blk - group * SPLITS;
    int ij     = group >> 4;
    int t      = threadIdx.x;
    int k      = t % Kdim;
    int a      = t / Kdim;                 // 0..15
    int lane   = t & 31;
    const float* base = yphi + (size_t)group * (Bdim * VK)
                             + (size_t)bsplit * BPB * VK + t;

    float regA[6] = {0.f, 0.f, 0.f, 0.f, 0.f, 0.f};
    float sG = 0.f;
    __shared__ float smG[T1];

    for (int b = 0; b < BPB; ++b) {
        const float* p = base + b * VK;
        float x0 = p[0],      x1 = p[T1],     x2 = p[2 * T1];
        float x3 = p[3 * T1], x4 = p[4 * T1], x5 = p[5 * T1];
        regA[0] += x0; regA[1] += x1; regA[2] += x2;
        regA[3] += x3; regA[4] += x4; regA[5] += x5;
        float s = ((x0 + x1) + (x2 + x3)) + (x4 + x5);
        sG += s;
        // block-wide sum for Wb[b]: warp reduce then one atomic per warp
#pragma unroll
        for (int off = 16; off; off >>= 1) s += __shfl_down_sync(0xffffffffu, s, off);
        if (lane == 0) atomicAdd(&g_Wb[ij * Bdim + bsplit * BPB + b], s);
    }
    // A[ij][v][k], v = a + 16*m
#pragma unroll
    for (int m = 0; m < 6; ++m) {
        int v = a + 16 * m;
        atomicAdd(&g_A[ij * VK + v * Kdim + k], regA[m]);
    }
    // G[group][k]: reduce sG over the 16 a-groups with equal k
    smG[t] = sG;
    __syncthreads();
    if (t < Kdim) {
        float g = 0.f;
#pragma unroll
        for (int aa = 0; aa < 16; ++aa) g += smG[aa * Kdim + t];
        atomicAdd(&g_G[group * Kdim + t], g);
    }
}

// ---------------------------------------------------------------------------
// Kernel 4: finisher — all parameter math + dot products, double accumulation
// ---------------------------------------------------------------------------
__global__ __launch_bounds__(256) void final_kernel(
    const float* __restrict__ T0p, const float* __restrict__ tp,
    const float* __restrict__ rp,  const float* __restrict__ ep,
    const float* __restrict__ enp, const float* __restrict__ ecp,
    const int*   __restrict__ index, float* __restrict__ out)
{
    __shared__ float sT0[VK], slt[VK], slr[VK];
    __shared__ float scol[Kdim];
    __shared__ float sinvZ[NIJ * Kdim];
    __shared__ float slqt[3 * Kdim], slqr[3 * Kdim];
    __shared__ float slpe[4 * Kdim], slpn[2 * Kdim], slpc[2 * Kdim];
    __shared__ float slmr[4 * Bdim];
    __shared__ double sred[256];
    int t = threadIdx.x;

    // exp(_T0), sigmoid(_t), sigmoid(_r)
    for (int idx = t; idx < VK; idx += 256) {
        sT0[idx] = __expf(T0p[idx]);
        slt[idx] = 1.f / (1.f + __expf(-tp[idx]));
        slr[idx] = 1.f / (1.f + __expf(-rp[idx]));
    }
    __syncthreads();
    // softmax column sums over V
    if (t < Kdim) {
        float s = 0.f;
        for (int v = 0; v < Vdim; ++v) s += sT0[v * Kdim + t];
        scol[t] = 1.f / s;
    }
    __syncthreads();
    for (int idx = t; idx < VK; idx += 256) sT0[idx] *= scol[idx % Kdim];
    __syncthreads();
    // Z[ij][k] = sum_v T0*wt_i*wr_j ; stored inverted
    if (t < NIJ * Kdim) {
        int ij = t / Kdim, k = t - ij * Kdim;
        int i = ij / 3, j = ij % 3;
        float s = 0.f;
        for (int v = 0; v < Vdim; ++v) {
            int r = v * Kdim + k;
            float wt = (i == 0) ? slt[r] : (i == 1) ? 1.f - slt[r] : 1.f;
            float wr = (j == 0) ? slr[r] : (j == 1) ? 1.f - slr[r] : 1.f;
            s += sT0[r] * wt * wr;
        }
        sinvZ[t] = 1.f / s;
    }
    __syncthreads();
    // log qt / log qr  (pt = Z[i=0,j=2], pr = Z[i=2,j=0]) and log-softmaxes
    if (t < Kdim) {
        float pt = 1.f / sinvZ[2 * Kdim + t];   // ij = 0*3+2
        float pr = 1.f / sinvZ[6 * Kdim + t];   // ij = 2*3+0
        slqt[t] = __logf(pt); slqt[Kdim + t] = __logf(1.f - pt); slqt[2 * Kdim + t] = 0.f;
        slqr[t] = __logf(pr); slqr[Kdim + t] = __logf(1.f - pr); slqr[2 * Kdim + t] = 0.f;
        float s, l;
        s = 0.f; for (int e = 0; e < 4; ++e) s += __expf(ep[e * Kdim + t]);
        l = __logf(s);
        for (int e = 0; e < 4; ++e) slpe[e * Kdim + t] = ep[e * Kdim + t] - l;
        s = 0.f; for (int n = 0; n < 2; ++n) s += __expf(enp[n * Kdim + t]);
        l = __logf(s);
        for (int n = 0; n < 2; ++n) slpn[n * Kdim + t] = enp[n * Kdim + t] - l;
        s = 0.f; for (int c = 0; c < 2; ++c) s += __expf(ecp[c * Kdim + t]);
        l = __logf(s);
        for (int c = 0; c < 2; ++c) slpc[c * Kdim + t] = ecp[c * Kdim + t] - l;
    }
    // missing rates (log), gathered per batch sample
    {
        int d = index[t];
        float y[9];
#pragma unroll
        for (int ij = 0; ij < 9; ++ij) y[ij] = g_ytr[ij * Ddim + d];
        float tot = ((y[0] + y[1]) + (y[2] + y[3])) + ((y[4] + y[5]) + (y[6] + y[7])) + y[8];
        float inv = 1.f / tot;
        slmr[t]           = __logf((y[0] + y[1] + y[3] + y[4]) * inv);  // m00
        slmr[256 + t]     = __logf((y[2] + y[5]) * inv);                // m01
        slmr[512 + t]     = __logf((y[6] + y[7]) * inv);                // m10
        slmr[768 + t]     = __logf(y[8] * inv);                         // m11
    }
    __syncthreads();

    double acc = 0.0;
    // term 1: A * (log T + log qt_i + log qr_j)
    for (int idx = t; idx < NIJ * VK; idx += 256) {
        int ij = idx / VK;
        int rem = idx - ij * VK;
        int i = ij / 3, j = ij % 3;
        int k = rem % Kdim;
        float wt = (i == 0) ? slt[rem] : (i == 1) ? 1.f - slt[rem] : 1.f;
        float wr = (j == 0) ? slr[rem] : (j == 1) ? 1.f - slr[rem] : 1.f;
        float tv = sT0[rem] * wt * wr * sinvZ[ij * Kdim + k];
        acc += (double)g_A[idx] *
               (double)(__logf(tv) + slqt[i * Kdim + k] + slqr[j * Kdim + k]);
    }
    // term 2: Wb * log mr3
    for (int idx = t; idx < NIJ * Bdim; idx += 256) {
        int ij = idx >> 8, b = idx & 255;
        int i = ij / 3, j = ij % 3;
        int sel = ((i == 2) ? 2 : 0) + ((j == 2) ? 1 : 0);
        acc += (double)g_Wb[idx] * (double)slmr[sel * Bdim + b];
    }
    // term 3: G * (log pe + log pn + log pc)
    for (int idx = t; idx < GROUPS * Kdim; idx += 256) {
        int grp = idx / Kdim, k = idx - grp * Kdim;
        int enc = grp & 15;
        int e = enc >> 2, n = (enc >> 1) & 1, c = enc & 1;
        acc += (double)g_G[idx] *
               (double)(slpe[e * Kdim + k] + slpn[n * Kdim + k] + slpc[c * Kdim + k]);
    }
    sred[t] = acc;
    __syncthreads();
    for (int off = 128; off; off >>= 1) {
        if (t < off) sred[t] += sred[t + off];
        __syncthreads();
    }
    if (t == 0) out[0] = (float)(-sred[0] / (double)VK);
}

// ---------------------------------------------------------------------------
extern "C" void kernel_launch(void* const* d_in, const int* in_sizes, int n_in,
                              void* d_out, int out_size) {
    (void)in_sizes; (void)n_in; (void)out_size;
    const float* yphi = (const float*)d_in[0];
    const float* Yv   = (const float*)d_in[1];
    const float* T0p  = (const float*)d_in[2];
    const float* tp   = (const float*)d_in[3];
    const float* rp   = (const float*)d_in[4];
    const float* ep   = (const float*)d_in[5];
    const float* enp  = (const float*)d_in[6];
    const float* ecp  = (const float*)d_in[7];
    const int*   idx  = (const int*)d_in[8];
    float* out = (float*)d_out;

    zero_scratch<<<(NIJ * VK + 255) / 256, 256>>>();
    reduce_Y<<<NIJ * Ddim, 96>>>(Yv);
    reduce_yphi<<<GROUPS * SPLITS, T1>>>(yphi);
    final_kernel<<<1, 256>>>(T0p, tp, rp, ep, enp, ecp, idx, out);
}

// round 4
// speedup vs baseline: 1.9032x; 1.9032x over previous
#include <cuda_runtime.h>

#define Vdim   96
#define Kdim   20
#define Bdim   256
#define Ddim   1024
#define NIJ    9
#define GROUPS 144      // 3*3*4*2*2
#define VK     1920     // Vdim*Kdim

// fused yphi kernel geometry
#define BPB    32               // b's per block
#define SPLITS (Bdim / BPB)     // 8
#define TFUSE  480              // 480 threads * 4 floats = 1920 = one (V,K) slab

// ---- scratch (static device globals — no runtime allocation) ----
__device__ float  g_ytr[NIJ * Ddim];     // sum over (e,n,c,v) of Y  -> [ij][d]
__device__ float  g_eT0[VK];             // exp(_T0)
__device__ float  g_lt[VK];              // sigmoid(_t)
__device__ float  g_lr[VK];              // sigmoid(_r)
__device__ float  g_invZ[NIJ * Kdim];    // 1 / sum_v eT0*wt*wr   (scol cancels in T)
__device__ float  g_lqt[3 * Kdim];       // log qt rows (third row = 0)
__device__ float  g_lqr[3 * Kdim];
__device__ float  g_L3[16 * Kdim];       // log pe + log pn + log pc per (enc,k)
__device__ float  g_lmr[4 * Bdim];       // log missing-rate per (sel,b)
__device__ float  g_L1[NIJ * VK];        // log T + log qt + log qr per (ij,v,k)
__device__ double g_loss;

// ---------------------------------------------------------------------------
// Kernel 1: reduce Y -> ytr, plus (extra blocks) exp/sigmoid tables + zero loss
// Y layout: (3,3,4,2,2,D,V); for fixed ij: enc stride = D*V, d stride = V.
// ---------------------------------------------------------------------------
__global__ __launch_bounds__(96) void k_reduceY_prepA(
    const float* __restrict__ Yv, const float* __restrict__ T0p,
    const float* __restrict__ tp, const float* __restrict__ rp)
{
    int blk = blockIdx.x, t = threadIdx.x;
    if (blk < NIJ * Ddim) {
        int ij = blk / Ddim;
        int d  = blk - ij * Ddim;
        const float* base = Yv + (size_t)ij * (16 * Ddim * Vdim) + (size_t)d * Vdim + t;
        float s = 0.f;
#pragma unroll
        for (int enc = 0; enc < 16; ++enc) s += base[(size_t)enc * Ddim * Vdim];
#pragma unroll
        for (int off = 16; off; off >>= 1) s += __shfl_down_sync(0xffffffffu, s, off);
        __shared__ float sm[3];
        if ((t & 31) == 0) sm[t >> 5] = s;
        __syncthreads();
        if (t == 0) g_ytr[blk] = sm[0] + sm[1] + sm[2];
    } else {
        int b2 = blk - NIJ * Ddim;          // 0..11
        if (b2 == 0 && t == 0) g_loss = 0.0;
        for (int i = b2 * 96 + t; i < VK; i += 12 * 96) {
            g_eT0[i] = __expf(T0p[i]);
            g_lt[i]  = 1.f / (1.f + __expf(-tp[i]));
            g_lr[i]  = 1.f / (1.f + __expf(-rp[i]));
        }
    }
}

// ---------------------------------------------------------------------------
// Kernel 2: tiny cross-element reductions + small log tables (1 block)
// ---------------------------------------------------------------------------
__global__ __launch_bounds__(1024) void k_prepZ(
    const float* __restrict__ ep, const float* __restrict__ enp,
    const float* __restrict__ ecp, const int* __restrict__ index)
{
    __shared__ float se[VK], st[VK], sr[VK];
    __shared__ float scolsum[Kdim];
    __shared__ float sZraw[NIJ * Kdim];
    int t = threadIdx.x, lane = t & 31, w = t >> 5;

    for (int i = t; i < VK; i += 1024) { se[i] = g_eT0[i]; st[i] = g_lt[i]; sr[i] = g_lr[i]; }
    __syncthreads();

    // column sums of eT0 over V (warp per column)
    if (w < Kdim) {
        float s = 0.f;
        for (int v = lane; v < Vdim; v += 32) s += se[v * Kdim + w];
#pragma unroll
        for (int off = 16; off; off >>= 1) s += __shfl_down_sync(0xffffffffu, s, off);
        if (lane == 0) scolsum[w] = s;
    }
    // raw Z[ij][k] (warp per output)
    for (int o = w; o < NIJ * Kdim; o += 32) {
        int ij = o / Kdim, k = o - ij * Kdim, i = ij / 3, j = ij % 3;
        float s = 0.f;
        for (int v = lane; v < Vdim; v += 32) {
            int r = v * Kdim + k;
            float wt = (i == 0) ? st[r] : (i == 1) ? 1.f - st[r] : 1.f;
            float wr = (j == 0) ? sr[r] : (j == 1) ? 1.f - sr[r] : 1.f;
            s += se[r] * wt * wr;
        }
#pragma unroll
        for (int off = 16; off; off >>= 1) s += __shfl_down_sync(0xffffffffu, s, off);
        if (lane == 0) sZraw[o] = s;
    }
    __syncthreads();

    if (t < NIJ * Kdim) g_invZ[t] = 1.f / sZraw[t];

    if (t < Kdim) {
        float inv = 1.f / scolsum[t];
        float pt = sZraw[2 * Kdim + t] * inv;   // ij = (0,2): wt=lt, wr=1
        float pr = sZraw[6 * Kdim + t] * inv;   // ij = (2,0): wt=1, wr=lr
        g_lqt[t] = __logf(pt); g_lqt[Kdim + t] = __logf(1.f - pt); g_lqt[2 * Kdim + t] = 0.f;
        g_lqr[t] = __logf(pr); g_lqr[Kdim + t] = __logf(1.f - pr); g_lqr[2 * Kdim + t] = 0.f;
        float lpe[4], lpn[2], lpc[2]; float s, l;
        s = 0.f; for (int e = 0; e < 4; ++e) s += __expf(ep[e * Kdim + t]);
        l = __logf(s);
        for (int e = 0; e < 4; ++e) lpe[e] = ep[e * Kdim + t] - l;
        s = 0.f; for (int n = 0; n < 2; ++n) s += __expf(enp[n * Kdim + t]);
        l = __logf(s);
        for (int n = 0; n < 2; ++n) lpn[n] = enp[n * Kdim + t] - l;
        s = 0.f; for (int c = 0; c < 2; ++c) s += __expf(ecp[c * Kdim + t]);
        l = __logf(s);
        for (int c = 0; c < 2; ++c) lpc[c] = ecp[c * Kdim + t] - l;
        for (int enc = 0; enc < 16; ++enc)
            g_L3[enc * Kdim + t] = lpe[enc >> 2] + lpn[(enc >> 1) & 1] + lpc[enc & 1];
    }
    // log missing-rates per batch sample
    if (t < Bdim) {
        int d = index[t];
        float y[9];
#pragma unroll
        for (int ij = 0; ij < 9; ++ij) y[ij] = g_ytr[ij * Ddim + d];
        float tot = ((y[0] + y[1]) + (y[2] + y[3])) + ((y[4] + y[5]) + (y[6] + y[7])) + y[8];
        float inv = 1.f / tot;
        g_lmr[t]            = __logf((y[0] + y[1] + y[3] + y[4]) * inv);  // m00
        g_lmr[Bdim + t]     = __logf((y[2] + y[5]) * inv);                // m01
        g_lmr[2 * Bdim + t] = __logf((y[6] + y[7]) * inv);                // m10
        g_lmr[3 * Bdim + t] = __logf(y[8] * inv);                         // m11
    }
}

// ---------------------------------------------------------------------------
// Kernel 3: L1[ij][v][k] = log T + log qt + log qr   (grid-parallel logs)
// ---------------------------------------------------------------------------
__global__ __launch_bounds__(384) void k_prepL1() {
    int idx = blockIdx.x * 384 + threadIdx.x;
    if (idx >= NIJ * VK) return;
    int ij  = idx / VK;
    int rem = idx - ij * VK;
    int k   = rem % Kdim;
    int i = ij / 3, j = ij % 3;
    float lt = g_lt[rem], lr = g_lr[rem];
    float wt = (i == 0) ? lt : (i == 1) ? 1.f - lt : 1.f;
    float wr = (j == 0) ? lr : (j == 1) ? 1.f - lr : 1.f;
    float tv = g_eT0[rem] * wt * wr * g_invZ[ij * Kdim + k];   // scol cancels
    g_L1[idx] = __logf(tv) + g_lqt[i * Kdim + k] + g_lqr[j * Kdim + k];
}

// ---------------------------------------------------------------------------
// Kernel 4: stream yphi once, dot against precomputed log tables.
// yphi: (3,3,e,n,c,B,V,K); group = ij*16+enc. 480 threads * float4 = one slab.
// ---------------------------------------------------------------------------
__global__ __launch_bounds__(TFUSE) void k_fused(const float* __restrict__ yphi) {
    int blk    = blockIdx.x;
    int group  = blk / SPLITS;
    int bsplit = blk - group * SPLITS;
    int ij  = group >> 4, enc = group & 15;
    int i = ij / 3, j = ij % 3;
    int sel = ((i == 2) ? 2 : 0) + ((j == 2) ? 1 : 0);
    int t = threadIdx.x;

    __shared__ float  sL3[Kdim];
    __shared__ float  slmr[BPB];
    __shared__ double sred[TFUSE / 32];
    if (t < Kdim) sL3[t]  = g_L3[enc * Kdim + t];
    if (t < BPB)  slmr[t] = g_lmr[sel * Bdim + bsplit * BPB + t];
    __syncthreads();

    // this thread's 4 fixed weights (k indices 4t%20 .. +3, never wrap)
    float4 wv = *(const float4*)(g_L1 + ij * VK + 4 * t);
    int kb = (4 * t) % Kdim;
    wv.x += sL3[kb]; wv.y += sL3[kb + 1]; wv.z += sL3[kb + 2]; wv.w += sL3[kb + 3];

    const float4* p = (const float4*)(yphi + (size_t)group * (Bdim * VK)
                                           + (size_t)bsplit * BPB * VK) + t;
    float acc = 0.f, acc2 = 0.f;
#pragma unroll 8
    for (int b = 0; b < BPB; ++b) {
        float4 x = p[(size_t)b * (VK / 4)];
        acc  += x.x * wv.x; acc += x.y * wv.y; acc += x.z * wv.z; acc += x.w * wv.w;
        acc2 += ((x.x + x.y) + (x.z + x.w)) * slmr[b];
    }
    float v = acc + acc2;
#pragma unroll
    for (int off = 16; off; off >>= 1) v += __shfl_down_sync(0xffffffffu, v, off);
    if ((t & 31) == 0) sred[t >> 5] = (double)v;
    __syncthreads();
    if (t == 0) {
        double s = 0.0;
#pragma unroll
        for (int w = 0; w < TFUSE / 32; ++w) s += sred[w];
        atomicAdd(&g_loss, s);
    }
}

__global__ void k_finish(float* __restrict__ out) {
    out[0] = (float)(-g_loss / (double)VK);
}

// ---------------------------------------------------------------------------
extern "C" void kernel_launch(void* const* d_in, const int* in_sizes, int n_in,
                              void* d_out, int out_size) {
    (void)in_sizes; (void)n_in; (void)out_size;
    const float* yphi = (const float*)d_in[0];
    const float* Yv   = (const float*)d_in[1];
    const float* T0p  = (const float*)d_in[2];
    const float* tp   = (const float*)d_in[3];
    const float* rp   = (const float*)d_in[4];
    const float* ep   = (const float*)d_in[5];
    const float* enp  = (const float*)d_in[6];
    const float* ecp  = (const float*)d_in[7];
    const int*   idx  = (const int*)d_in[8];
    float* out = (float*)d_out;

    k_reduceY_prepA<<<NIJ * Ddim + 12, 96>>>(Yv, T0p, tp, rp);
    k_prepZ<<<1, 1024>>>(ep, enp, ecp, idx);
    k_prepL1<<<(NIJ * VK + 383) / 384, 384>>>();
    k_fused<<<GROUPS * SPLITS, TFUSE>>>(yphi);
    k_finish<<<1, 1>>>(out);
}